// round 3
// baseline (speedup 1.0000x reference)
#include <cuda_runtime.h>
#include <cstdint>

// PosRegressor_43482248904949 — batched bilinear shift with mirror boundary.
// images: (256,512,512,1) fp32, dxdy: (256,2) fp32 -> out: (256,512,512) fp32.
//
// R3: exploit that dx,dy are per-image SCALARS:
//   floor(x - dx) = x + floor(-dx)  (exact, x integer)
//   fx = frac(-dx)                  (constant per image)
// => output row = constant-weight bilinear blend of two integer-shifted input
// rows. Stage shifted+mirrored rows in smem (vector LDG.128), compute with
// 4 FMA/pixel and LDS.128/STG.128. Mirror ALU only in tiny halo loops.

#define H 512
#define W 512
#define ROWS 4                 // output rows per block
#define SROWS (ROWS + 1)       // staged input rows
#define EXTW (W + 4)           // staged row: need [0, W], padded to 516 (16B mult)
#define NTHREADS 256

__device__ __forceinline__ int mirror_idx(int idx, int n) {
    const int p = 2 * (n - 1);
    int i = idx < 0 ? -idx : idx;
    i %= p;
    return (i >= n) ? (p - i) : i;
}

__global__ void __launch_bounds__(NTHREADS)
shift_bilinear_kernel(const float* __restrict__ img,
                      const float* __restrict__ dxdy,
                      float* __restrict__ out) {
    __shared__ __align__(16) float sm[SROWS][EXTW];

    const int b   = blockIdx.y;
    const int yb  = blockIdx.x * ROWS;
    const int tid = threadIdx.x;

    const float dy = dxdy[2 * b + 0];
    const float dx = dxdy[2 * b + 1];

    const float ndx = -dx, ndy = -dy;
    const float kxf = floorf(ndx); const int kx = (int)kxf; const float fx = ndx - kxf;
    const float kyf = floorf(ndy); const int ky = (int)kyf; const float fy = ndy - kyf;

    const size_t base = (size_t)b * (H * W);

    // ---- Stage: sm[r][j] = img[b, mirror(yb+ky+r, H), mirror(j+kx, W)], j in [0, W]
    // Interior (j+kx in [0,W)): vectorized copy of the raw row shifted by -kx.
    for (int idx = tid; idx < SROWS * (W / 4); idx += NTHREADS) {
        const int r  = idx >> 7;              // W/4 = 128 chunks per row
        const int i4 = (idx & 127) << 2;      // aligned source column
        const int ry = mirror_idx(yb + ky + r, H);
        const float4 v = *reinterpret_cast<const float4*>(img + base + (size_t)ry * W + i4);
        const int j = i4 - kx;
        float* e = sm[r];
        if (j >= 0 && j + 3 < EXTW) {
            e[j] = v.x; e[j + 1] = v.y; e[j + 2] = v.z; e[j + 3] = v.w;
        } else {
            if (j     >= 0 && j     < EXTW) e[j]     = v.x;
            if (j + 1 >= 0 && j + 1 < EXTW) e[j + 1] = v.y;
            if (j + 2 >= 0 && j + 2 < EXTW) e[j + 2] = v.z;
            if (j + 3 >= 0 && j + 3 < EXTW) e[j + 3] = v.w;
        }
    }

    // Halo fix-ups: j in [0, W] with j+kx outside [0, W). For dx~N(0,1) this is
    // <= ~5 columns; code is fully general (covers any kx).
    {
        const int n1  = max(0, min(-kx, W + 1));   // lower: j in [0, n1)
        const int hi0 = max(0, W - kx);            // upper: j in [hi0, W]
        const int n2  = max(0, W + 1 - max(hi0, n1));
        const int tot = n1 + n2;
        #pragma unroll
        for (int r = 0; r < SROWS; ++r) {
            const int ry = mirror_idx(yb + ky + r, H);
            const float* grow = img + base + (size_t)ry * W;
            for (int m = tid; m < tot; m += NTHREADS) {
                const int j = (m < n1) ? m : (hi0 + (m - n1));
                sm[r][j] = grow[mirror_idx(j + kx, W)];
            }
        }
    }

    __syncthreads();

    // ---- Compute: 4 rows x 512 cols, 8 px/thread, constant weights.
    const int trow = tid >> 6;            // 0..3
    const int cb   = (tid & 63) << 3;     // 0,8,...,504

    const float omfy = 1.0f - fy, omfx = 1.0f - fx;
    const float w00 = omfy * omfx, w01 = omfy * fx;
    const float w10 = fy * omfx,   w11 = fy * fx;

    const float* e0 = sm[trow];
    const float* e1 = sm[trow + 1];

    float r0[9], r1[9];
    {
        float4 a = *reinterpret_cast<const float4*>(&e0[cb]);
        float4 c = *reinterpret_cast<const float4*>(&e0[cb + 4]);
        r0[0]=a.x; r0[1]=a.y; r0[2]=a.z; r0[3]=a.w;
        r0[4]=c.x; r0[5]=c.y; r0[6]=c.z; r0[7]=c.w;
        r0[8]=e0[cb + 8];
        float4 d = *reinterpret_cast<const float4*>(&e1[cb]);
        float4 g = *reinterpret_cast<const float4*>(&e1[cb + 4]);
        r1[0]=d.x; r1[1]=d.y; r1[2]=d.z; r1[3]=d.w;
        r1[4]=g.x; r1[5]=g.y; r1[6]=g.z; r1[7]=g.w;
        r1[8]=e1[cb + 8];
    }

    float o[8];
    #pragma unroll
    for (int p = 0; p < 8; ++p)
        o[p] = fmaf(w00, r0[p], fmaf(w01, r0[p + 1],
               fmaf(w10, r1[p], w11 * r1[p + 1])));

    float* op = out + base + (size_t)(yb + trow) * W + cb;
    *reinterpret_cast<float4*>(op)     = make_float4(o[0], o[1], o[2], o[3]);
    *reinterpret_cast<float4*>(op + 4) = make_float4(o[4], o[5], o[6], o[7]);
}

extern "C" void kernel_launch(void* const* d_in, const int* in_sizes, int n_in,
                              void* d_out, int out_size) {
    const float* images = (const float*)d_in[0];  // (256,512,512,1)
    const float* dxdy   = (const float*)d_in[1];  // (256,2)
    float* out = (float*)d_out;                   // (256,512,512)

    const int B = in_sizes[1] / 2;                // 256
    dim3 grid(H / ROWS, B);
    shift_bilinear_kernel<<<grid, NTHREADS>>>(images, dxdy, out);
}

// round 4
// speedup vs baseline: 1.0489x; 1.0489x over previous
#include <cuda_runtime.h>
#include <cstdint>

// PosRegressor_43482248904949 — batched bilinear shift with mirror boundary.
// images: (256,512,512,1) fp32, dxdy: (256,2) fp32 -> out: (256,512,512) fp32.
//
// R4: constant-shift algorithm (dx,dy scalar per image => integer shift kx,ky +
// constant weights), with CONFLICT-FREE smem patterns:
//  - staging: scalar LDG.32/STS.32, lane-consecutive (coalesced + 32 banks)
//  - compute: warp-per-row, lane-contiguous LDS.128/STG.128 (zero conflicts)

#define H 512
#define W 512
#define ROWS 8                  // output rows per block (1 warp per row)
#define SROWS (ROWS + 1)        // staged input rows
#define EXTW 516                // need t in [0,512]; pad to 516 (16B multiple)
#define NTHREADS 256

__device__ __forceinline__ int mirror_idx(int idx, int n) {
    const int p = 2 * (n - 1);
    int i = idx < 0 ? -idx : idx;
    i %= p;
    return (i >= n) ? (p - i) : i;
}

__global__ void __launch_bounds__(NTHREADS)
shift_bilinear_kernel(const float* __restrict__ img,
                      const float* __restrict__ dxdy,
                      float* __restrict__ out) {
    __shared__ __align__(16) float sm[SROWS][EXTW];

    const int b   = blockIdx.y;
    const int yb  = blockIdx.x * ROWS;
    const int tid = threadIdx.x;

    const float dy = dxdy[2 * b + 0];
    const float dx = dxdy[2 * b + 1];

    const float ndx = -dx, ndy = -dy;
    const float kxf = floorf(ndx); const int kx = (int)kxf; const float fx = ndx - kxf;
    const float kyf = floorf(ndy); const int ky = (int)kyf; const float fy = ndy - kyf;

    const size_t base = (size_t)b * (H * W);

    // ---- Stage: sm[r][t] = img[b, mirror(yb+ky+r, H), mirror(kx+t, W)], t in [0,513)
    // Interior range [lo,hi): kx+t in [0,W) -> direct consecutive copy (coalesced,
    // conflict-free). Halo (mirror) only for the few out-of-range t.
    {
        int lo = max(0, -kx); lo = min(lo, W + 1);
        int hi = min(W + 1, W - kx); hi = max(hi, lo);
        #pragma unroll
        for (int r = 0; r < SROWS; ++r) {
            const int ry = mirror_idx(yb + ky + r, H);
            const float* __restrict__ grow = img + base + (size_t)ry * W;
            float* __restrict__ srow = sm[r];
            for (int t = lo + tid; t < hi; t += NTHREADS)
                srow[t] = __ldg(grow + (kx + t));
            for (int t = tid; t < lo; t += NTHREADS)
                srow[t] = grow[mirror_idx(kx + t, W)];
            for (int t = hi + tid; t < W + 1; t += NTHREADS)
                srow[t] = grow[mirror_idx(kx + t, W)];
        }
    }

    __syncthreads();

    // ---- Compute: warp w -> output row yb+w. Lane-contiguous float4 groups.
    const int wrow = tid >> 5;            // 0..7
    const int lane = tid & 31;

    const float omfy = 1.0f - fy, omfx = 1.0f - fx;
    const float w00 = omfy * omfx, w01 = omfy * fx;
    const float w10 = fy * omfx,   w11 = fy * fx;

    const float* __restrict__ e0 = sm[wrow];
    const float* __restrict__ e1 = sm[wrow + 1];
    float* __restrict__ op = out + base + (size_t)(yb + wrow) * W;

    #pragma unroll
    for (int g = 0; g < 4; ++g) {
        const int j = 128 * g + 4 * lane;     // lanes contiguous: 16B stride
        const float4 a0 = *reinterpret_cast<const float4*>(e0 + j);
        const float4 b0 = *reinterpret_cast<const float4*>(e0 + j + 4);
        const float4 a1 = *reinterpret_cast<const float4*>(e1 + j);
        const float4 b1 = *reinterpret_cast<const float4*>(e1 + j + 4);

        float4 o;
        o.x = fmaf(w00, a0.x, fmaf(w01, a0.y, fmaf(w10, a1.x, w11 * a1.y)));
        o.y = fmaf(w00, a0.y, fmaf(w01, a0.z, fmaf(w10, a1.y, w11 * a1.z)));
        o.z = fmaf(w00, a0.z, fmaf(w01, a0.w, fmaf(w10, a1.z, w11 * a1.w)));
        o.w = fmaf(w00, a0.w, fmaf(w01, b0.x, fmaf(w10, a1.w, w11 * b1.x)));
        *reinterpret_cast<float4*>(op + j) = o;
    }
}

extern "C" void kernel_launch(void* const* d_in, const int* in_sizes, int n_in,
                              void* d_out, int out_size) {
    const float* images = (const float*)d_in[0];  // (256,512,512,1)
    const float* dxdy   = (const float*)d_in[1];  // (256,2)
    float* out = (float*)d_out;                   // (256,512,512)

    const int B = in_sizes[1] / 2;                // 256
    dim3 grid(H / ROWS, B);
    shift_bilinear_kernel<<<grid, NTHREADS>>>(images, dxdy, out);
}

// round 5
// speedup vs baseline: 1.3241x; 1.2624x over previous
#include <cuda_runtime.h>
#include <cstdint>

// PosRegressor_43482248904949 — batched bilinear shift with mirror boundary.
// images: (256,512,512,1) fp32, dxdy: (256,2) fp32 -> out: (256,512,512) fp32.
//
// R5: same constant-shift algorithm (dx,dy scalar per image => integer shift +
// constant weights), staging rewritten for deep MLP:
//  - cp.async (LDGSTS) global->shared, 18 per-thread copies front-batched,
//    no LDG->STS register dependency, single wait.
//  - fully static unrolled staging (no dynamic-bound loops).
//  - mirror halo via rare predicated scalar path.
// Compute phase: warp-per-row, lane-contiguous LDS.128/STG.128 (conflict-free).

#define H 512
#define W 512
#define ROWS 8                  // output rows per block (1 warp per row)
#define SROWS (ROWS + 1)        // staged input rows
#define EXTW 516                // t in [0,512]; pad to 516 (16B multiple)
#define NTHREADS 256

__device__ __forceinline__ int mirror_idx(int idx, int n) {
    const int p = 2 * (n - 1);
    int i = idx < 0 ? -idx : idx;
    i %= p;
    return (i >= n) ? (p - i) : i;
}

__device__ __forceinline__ void cp_async4(void* sptr, const void* gptr) {
    const unsigned saddr = (unsigned)__cvta_generic_to_shared(sptr);
    asm volatile("cp.async.ca.shared.global [%0], [%1], 4;"
                 :: "r"(saddr), "l"(gptr));
}

// Stage one element: sm_row[t] = grow[mirror(kx+t, W)].
// Interior (no mirror) -> cp.async; halo -> scalar load+store (rare lanes).
__device__ __forceinline__ void stage_elem(float* __restrict__ srow,
                                           const float* __restrict__ grow,
                                           int kx, int t) {
    const int s = kx + t;
    if (s >= 0 && s < W) {
        cp_async4(srow + t, grow + s);
    } else {
        srow[t] = grow[mirror_idx(s, W)];
    }
}

__global__ void __launch_bounds__(NTHREADS)
shift_bilinear_kernel(const float* __restrict__ img,
                      const float* __restrict__ dxdy,
                      float* __restrict__ out) {
    __shared__ __align__(16) float sm[SROWS][EXTW];

    const int b   = blockIdx.y;
    const int yb  = blockIdx.x * ROWS;
    const int tid = threadIdx.x;

    const float dy = dxdy[2 * b + 0];
    const float dx = dxdy[2 * b + 1];

    const float ndx = -dx, ndy = -dy;
    const float kxf = floorf(ndx); const int kx = (int)kxf; const float fx = ndx - kxf;
    const float kyf = floorf(ndy); const int ky = (int)kyf; const float fy = ndy - kyf;

    const size_t base = (size_t)b * (H * W);

    // Mirrored row pointers (9 registers).
    const float* grow[SROWS];
    #pragma unroll
    for (int r = 0; r < SROWS; ++r)
        grow[r] = img + base + (size_t)mirror_idx(yb + ky + r, H) * W;

    // ---- Stage: sm[r][t] = row_r[mirror(kx+t)], t in [0,513).
    // 18 cp.asyncs per thread issued back-to-back (deep MLP), + 9-elem tail.
    #pragma unroll
    for (int r = 0; r < SROWS; ++r) {
        stage_elem(sm[r], grow[r], kx, tid);
        stage_elem(sm[r], grow[r], kx, tid + 256);
    }
    if (tid < SROWS)
        stage_elem(sm[tid], grow[tid], kx, 512);

    asm volatile("cp.async.commit_group;\n\tcp.async.wait_group 0;" ::: "memory");
    __syncthreads();

    // ---- Compute: warp w -> output row yb+w. Lane-contiguous float4 groups.
    const int wrow = tid >> 5;            // 0..7
    const int lane = tid & 31;

    const float omfy = 1.0f - fy, omfx = 1.0f - fx;
    const float w00 = omfy * omfx, w01 = omfy * fx;
    const float w10 = fy * omfx,   w11 = fy * fx;

    const float* __restrict__ e0 = sm[wrow];
    const float* __restrict__ e1 = sm[wrow + 1];
    float* __restrict__ op = out + base + (size_t)(yb + wrow) * W;

    #pragma unroll
    for (int g = 0; g < 4; ++g) {
        const int j = 128 * g + 4 * lane;     // lanes contiguous: 16B stride
        const float4 a0 = *reinterpret_cast<const float4*>(e0 + j);
        const float4 b0 = *reinterpret_cast<const float4*>(e0 + j + 4);
        const float4 a1 = *reinterpret_cast<const float4*>(e1 + j);
        const float4 b1 = *reinterpret_cast<const float4*>(e1 + j + 4);

        float4 o;
        o.x = fmaf(w00, a0.x, fmaf(w01, a0.y, fmaf(w10, a1.x, w11 * a1.y)));
        o.y = fmaf(w00, a0.y, fmaf(w01, a0.z, fmaf(w10, a1.y, w11 * a1.z)));
        o.z = fmaf(w00, a0.z, fmaf(w01, a0.w, fmaf(w10, a1.z, w11 * a1.w)));
        o.w = fmaf(w00, a0.w, fmaf(w01, b0.x, fmaf(w10, a1.w, w11 * b1.x)));
        *reinterpret_cast<float4*>(op + j) = o;
    }
}

extern "C" void kernel_launch(void* const* d_in, const int* in_sizes, int n_in,
                              void* d_out, int out_size) {
    const float* images = (const float*)d_in[0];  // (256,512,512,1)
    const float* dxdy   = (const float*)d_in[1];  // (256,2)
    float* out = (float*)d_out;                   // (256,512,512)

    const int B = in_sizes[1] / 2;                // 256
    dim3 grid(H / ROWS, B);
    shift_bilinear_kernel<<<grid, NTHREADS>>>(images, dxdy, out);
}

// round 6
// speedup vs baseline: 1.7080x; 1.2899x over previous
#include <cuda_runtime.h>
#include <cstdint>

// PosRegressor_43482248904949 — batched bilinear shift with mirror boundary.
// images: (256,512,512,1) fp32, dxdy: (256,2) fp32 -> out: (256,512,512) fp32.
//
// R6: no shared memory at all. dx,dy are per-image scalars => integer shift
// (kx,ky) + constant weights (fx,fy). Each thread owns 2 output columns and
// register-marches 9 mirrored input rows:
//   - 36 independent scalar LDGs (deep MLP; +1 neighbor is an L1 hit)
//   - horizontal lerp in regs, vertical lerp in regs
//   - 16 coalesced STG.32
// Kills the R5 L1 bottleneck (LDGSTS issue cost + double-read LDS traffic).

#define H 512
#define W 512
#define ROWS 8                  // output rows per block
#define SROWS (ROWS + 1)        // input rows touched
#define NTHREADS 256

__device__ __forceinline__ int mirror_idx(int idx, int n) {
    const int p = 2 * (n - 1);
    int i = idx < 0 ? -idx : idx;
    i %= p;
    return (i >= n) ? (p - i) : i;
}

// Load row[s] with mirror; interior fast path (predicated, edge lanes only).
__device__ __forceinline__ float ldm(const float* __restrict__ row, int s) {
    const int sm = (s >= 0 && s < W) ? s : mirror_idx(s, W);
    return __ldg(row + sm);
}

__global__ void __launch_bounds__(NTHREADS, 4)
shift_bilinear_kernel(const float* __restrict__ img,
                      const float* __restrict__ dxdy,
                      float* __restrict__ out) {
    const int b   = blockIdx.y;
    const int yb  = blockIdx.x * ROWS;
    const int tid = threadIdx.x;

    const float dy = dxdy[2 * b + 0];
    const float dx = dxdy[2 * b + 1];

    const float ndx = -dx, ndy = -dy;
    const float kxf = floorf(ndx); const int kx = (int)kxf; const float fx = ndx - kxf;
    const float kyf = floorf(ndy); const int ky = (int)kyf; const float fy = ndy - kyf;

    const size_t base = (size_t)b * (H * W);

    // Mirrored input row pointers.
    const float* grow[SROWS];
    #pragma unroll
    for (int r = 0; r < SROWS; ++r)
        grow[r] = img + base + (size_t)mirror_idx(yb + ky + r, H) * W;

    const int c0 = kx + tid;          // column position A (lane-consecutive)
    const int c1 = c0 + 256;          // column position B

    // Load + horizontal lerp for all 9 rows (loads are independent -> MLP).
    float hA[SROWS], hB[SROWS];
    #pragma unroll
    for (int r = 0; r < SROWS; ++r) {
        const float va = ldm(grow[r], c0);
        const float na = ldm(grow[r], c0 + 1);
        const float vb = ldm(grow[r], c1);
        const float nb = ldm(grow[r], c1 + 1);
        hA[r] = fmaf(fx, na - va, va);
        hB[r] = fmaf(fx, nb - vb, vb);
    }

    // Vertical lerp + coalesced stores.
    float* __restrict__ orow = out + base + (size_t)yb * W + tid;
    #pragma unroll
    for (int r = 0; r < ROWS; ++r) {
        orow[0]   = fmaf(fy, hA[r + 1] - hA[r], hA[r]);
        orow[256] = fmaf(fy, hB[r + 1] - hB[r], hB[r]);
        orow += W;
    }
}

extern "C" void kernel_launch(void* const* d_in, const int* in_sizes, int n_in,
                              void* d_out, int out_size) {
    const float* images = (const float*)d_in[0];  // (256,512,512,1)
    const float* dxdy   = (const float*)d_in[1];  // (256,2)
    float* out = (float*)d_out;                   // (256,512,512)

    const int B = in_sizes[1] / 2;                // 256
    dim3 grid(H / ROWS, B);
    shift_bilinear_kernel<<<grid, NTHREADS>>>(images, dxdy, out);
}